// round 3
// baseline (speedup 1.0000x reference)
#include <cuda_runtime.h>
#include <cstdint>

// CenterLoss: BATCH=4096, FEAT_DIM=256, NUM_CLASSES=8192
#define BATCH       4096
#define FEAT_DIM    256
#define NUM_CLASSES 8192
#define NBLOCKS     256          // 8 warps/block, 2 samples/warp
#define SCALE       268435456.0  // 2^28 fixed-point scale

// Per-block partials (distinct addresses -> no atomic contention) + counter.
__device__ unsigned long long g_part[NBLOCKS];
__device__ unsigned int       g_count = 0u;

__global__ void __launch_bounds__(256) center_loss_fused(
    const float* __restrict__ x,
    const void*  __restrict__ labels_raw,
    const float* __restrict__ centers,
    float*       __restrict__ out)
{
    const int lane = threadIdx.x & 31;
    const int warp = threadIdx.x >> 5;              // 0..7
    const int gw   = blockIdx.x * 8 + warp;         // warp id, 0..2047
    const int s0   = 2 * gw;                        // sample ids s0, s0+1

    // ---- speculative label-pair load (words 2gw, 2gw+1):
    //  in-bounds for BOTH layouts (i32: 4096 words, 2gw+1 <= 4095;
    //  i64: 8192 words). i32 layout => (label_s0, label_s1).
    const int2 li32 = ((const int2*)labels_raw)[gw];

    // ---- dtype probe (same 8 words for every warp -> L2-broadcast cached)
    int probe = (lane < 8) ? ((const int*)labels_raw)[2 * lane + 1] : 0;

    // ---- x loads: independent of labels, issue early.
    const float4* xr = (const float4*)(x + (size_t)s0 * FEAT_DIM);
    float4 a00 = xr[lane];
    float4 a01 = xr[lane + 32];
    float4 a10 = xr[lane + 64];   // sample s1 first half
    float4 a11 = xr[lane + 96];   // sample s1 second half

    const bool labels_i64 = (__ballot_sync(0xFFFFFFFFu, probe != 0) == 0);

    int l0, l1;
    if (labels_i64) {
        // words 4gw..4gw+3 : only safe under i64 layout (8192 words)
        int4 p = ((const int4*)labels_raw)[gw];
        l0 = p.x; l1 = p.z;
    } else {
        l0 = li32.x; l1 = li32.y;
    }

    const float4* c0 = (const float4*)(centers + (size_t)l0 * FEAT_DIM);
    const float4* c1 = (const float4*)(centers + (size_t)l1 * FEAT_DIM);
    float4 b00 = c0[lane];
    float4 b01 = c0[lane + 32];
    float4 b10 = c1[lane];
    float4 b11 = c1[lane + 32];

    float acc0 = 0.0f, acc1 = 0.0f, d;
    d = a00.x - b00.x; acc0 = fmaf(d, d, acc0);
    d = a00.y - b00.y; acc0 = fmaf(d, d, acc0);
    d = a00.z - b00.z; acc0 = fmaf(d, d, acc0);
    d = a00.w - b00.w; acc0 = fmaf(d, d, acc0);
    d = a01.x - b01.x; acc0 = fmaf(d, d, acc0);
    d = a01.y - b01.y; acc0 = fmaf(d, d, acc0);
    d = a01.z - b01.z; acc0 = fmaf(d, d, acc0);
    d = a01.w - b01.w; acc0 = fmaf(d, d, acc0);
    d = a10.x - b10.x; acc1 = fmaf(d, d, acc1);
    d = a10.y - b10.y; acc1 = fmaf(d, d, acc1);
    d = a10.z - b10.z; acc1 = fmaf(d, d, acc1);
    d = a10.w - b10.w; acc1 = fmaf(d, d, acc1);
    d = a11.x - b11.x; acc1 = fmaf(d, d, acc1);
    d = a11.y - b11.y; acc1 = fmaf(d, d, acc1);
    d = a11.z - b11.z; acc1 = fmaf(d, d, acc1);
    d = a11.w - b11.w; acc1 = fmaf(d, d, acc1);

#pragma unroll
    for (int o = 16; o > 0; o >>= 1) {
        acc0 += __shfl_xor_sync(0xFFFFFFFFu, acc0, o);
        acc1 += __shfl_xor_sync(0xFFFFFFFFu, acc1, o);
    }

    // ---- per-warp fixed-point partial (clamp per sample, faithful to ref)
    __shared__ unsigned long long s[8];
    if (lane == 0) {
        float v0 = fminf(fmaxf(acc0, 1e-12f), 1e12f);
        float v1 = fminf(fmaxf(acc1, 1e-12f), 1e12f);
        s[warp] = (unsigned long long)((double)v0 * SCALE)
                + (unsigned long long)((double)v1 * SCALE);
    }
    __syncthreads();

    // ---- warp 0: block partial -> distinct global slot, count, maybe final
    if (warp == 0) {
        unsigned long long w = (lane < 8) ? s[lane] : 0ull;
#pragma unroll
        for (int o = 4; o > 0; o >>= 1)
            w += __shfl_xor_sync(0xFFFFFFFFu, w, o);

        unsigned int old = 0u;
        if (lane == 0) {
            g_part[blockIdx.x] = w;
            __threadfence();
            old = atomicAdd(&g_count, 1u);
        }
        old = __shfl_sync(0xFFFFFFFFu, old, 0);

        if (old == NBLOCKS - 1) {
            // last block: parallel reduce of 256 partials (8 per lane)
            unsigned long long t = 0ull;
#pragma unroll
            for (int i = 0; i < NBLOCKS / 32; i++)
                t += g_part[lane + 32 * i];
#pragma unroll
            for (int o = 16; o > 0; o >>= 1)
                t += __shfl_xor_sync(0xFFFFFFFFu, t, o);
            if (lane == 0) {
                double loss = ((double)t / SCALE) / (double)BATCH
                            + (double)(NUM_CLASSES - 1) * 1e-12;
                out[0] = (float)loss;
                g_count = 0u;   // reset for next graph replay
            }
        }
    }
}

extern "C" void kernel_launch(void* const* d_in, const int* in_sizes, int n_in,
                              void* d_out, int out_size)
{
    const float* x       = (const float*)d_in[0];
    const void*  labels  = d_in[1];
    const float* centers = (const float*)d_in[2];
    float*       out     = (float*)d_out;
    (void)in_sizes; (void)n_in; (void)out_size;

    center_loss_fused<<<NBLOCKS, 256>>>(x, labels, centers, out);
}